// round 6
// baseline (speedup 1.0000x reference)
#include <cuda_runtime.h>
#include <math.h>

#define DIN  128
#define DH   128
#define DOUT 16
#define NCAP 100352
#define ECAP 1600128

// ---- scratch (static __device__ per harness rules) ----
__device__ int   g_is64;            // 1 if edge_index is int64, 0 if int32
__device__ int   g_deg[NCAP];
__device__ float g_dinv[NCAP];
__device__ int   g_incl[NCAP];
__device__ int   g_bsums[256];
__device__ int   g_boff[256];
__device__ int   g_rowptr[NCAP + 1];
__device__ int   g_cursor[NCAP];
__device__ int   g_col[ECAP];
__device__ __align__(16) float g_h1[(size_t)NCAP * DH];   // x@W1 (unscaled)
__device__ __align__(16) float g_a1[(size_t)NCAP * DH];   // relu(agg1 + b1)
__device__ __align__(16) float g_h2[(size_t)NCAP * DOUT]; // (a1@W2) * dinv[row]

// ------------------------------------------------------------------
// init: zero degree array; block 0 also detects edge_index dtype
// (int64 => high word of every entry is 0 since indices < 100K).
__global__ void k_init(const int* __restrict__ ei32, int e, int n) {
    int i = blockIdx.x * blockDim.x + threadIdx.x;
    if (i < n) g_deg[i] = 0;
    if (blockIdx.x == 0) {
        __shared__ int nz;
        if (threadIdx.x == 0) nz = 0;
        __syncthreads();
        int lim = (e < 4096) ? e : 4096;
        for (int t = threadIdx.x; t < lim; t += blockDim.x)
            if (ei32[2 * t + 1] != 0) nz = 1;   // benign race
        __syncthreads();
        if (threadIdx.x == 0) g_is64 = (nz == 0) ? 1 : 0;
    }
}

__device__ __forceinline__ int edge_at(const void* ei, size_t pos) {
    if (g_is64) return (int)((const long long*)ei)[pos];
    return ((const int*)ei)[pos];
}

// ------------------------------------------------------------------
// FMA4: acc += scal * vec  (parameter names must NOT collide with x/y/z/w)
#define FMA4(acc, vec, scal) do { \
    (acc).x = fmaf((scal), (vec).x, (acc).x); \
    (acc).y = fmaf((scal), (vec).y, (acc).y); \
    (acc).z = fmaf((scal), (vec).z, (acc).z); \
    (acc).w = fmaf((scal), (vec).w, (acc).w); } while (0)

#define KC 32        // k-chunk size for GEMM1
#define GD_BLOCKS 296  // degree-count blocks appended after the GEMM blocks

// Fused: blocks [0, g1) compute GEMM1 tile (h1 = x@W1, unscaled);
// blocks [g1, g1+GD_BLOCKS) do the degree histogram (independent work,
// runs concurrently on other SMs — capture-safe "overlap" on one stream).
__global__ void __launch_bounds__(256, 1) k_gemm1_deg(const float* __restrict__ x,
                                                      const float* __restrict__ W1,
                                                      const void* __restrict__ ei,
                                                      int e, int n, int g1) {
    __shared__ float Ws[KC * DH];    // 16KB
    __shared__ float Xs[128 * KC];   // 16KB

    if (blockIdx.x >= g1) {
        // ---- degree path ----
        int tid = (blockIdx.x - g1) * blockDim.x + threadIdx.x;
        int stride = GD_BLOCKS * blockDim.x;
        for (int i = tid; i < e; i += stride) {
            int d = edge_at(ei, (size_t)e + i);
            if ((unsigned)d < (unsigned)n) atomicAdd(&g_deg[d], 1);
        }
        return;
    }

    // ---- GEMM1 path ----
    int row0 = blockIdx.x * 128;
    int tx = threadIdx.x & 15;
    int ty = threadIdx.x >> 4;
    float4 a0[8], a1[8];
    #pragma unroll
    for (int r = 0; r < 8; r++) { a0[r] = make_float4(0,0,0,0); a1[r] = make_float4(0,0,0,0); }

    const float4* W4 = (const float4*)W1;
    const float4* x4 = (const float4*)x;
    float4* Ws4 = (float4*)Ws;
    float4* Xs4 = (float4*)Xs;

    for (int kc = 0; kc < DIN / KC; kc++) {
        for (int i = threadIdx.x; i < KC * DH / 4; i += 256)
            Ws4[i] = W4[kc * (KC * DH / 4) + i];
        for (int i = threadIdx.x; i < 128 * KC / 4; i += 256) {
            int r = i >> 3, c = i & 7, gr = row0 + r;
            Xs4[i] = (gr < n) ? x4[(size_t)gr * 32 + kc * 8 + c]
                              : make_float4(0.f, 0.f, 0.f, 0.f);
        }
        __syncthreads();

        const float* wp = Ws + tx * 8;
        #pragma unroll
        for (int k = 0; k < KC; k++) {
            float4 wv0 = *(const float4*)(wp + k * 128);
            float4 wv1 = *(const float4*)(wp + k * 128 + 4);
            #pragma unroll
            for (int r = 0; r < 8; r++) {
                float xv = Xs[(ty * 8 + r) * KC + k];
                FMA4(a0[r], wv0, xv);
                FMA4(a1[r], wv1, xv);
            }
        }
        __syncthreads();
    }

    #pragma unroll
    for (int r = 0; r < 8; r++) {
        int row = row0 + ty * 8 + r;
        if (row < n) {
            float4* hp = (float4*)&g_h1[(size_t)row * DH];
            hp[tx * 2]     = a0[r];
            hp[tx * 2 + 1] = a1[r];
        }
    }
}

// ------------------------------------------------------------------
// block-level inclusive scan (1024 elems / block) + dinv computation
__global__ void k_scan1(int n) {
    __shared__ int s[1024];
    int i = blockIdx.x * 1024 + threadIdx.x;
    int d = (i < n) ? g_deg[i] : 0;
    s[threadIdx.x] = d;
    if (i < n) g_dinv[i] = rsqrtf((float)(d + 1)); // +1 self loop
    __syncthreads();
    for (int off = 1; off < 1024; off <<= 1) {
        int t = (threadIdx.x >= off) ? s[threadIdx.x - off] : 0;
        __syncthreads();
        s[threadIdx.x] += t;
        __syncthreads();
    }
    if (i < n) g_incl[i] = s[threadIdx.x];
    if (threadIdx.x == 1023) g_bsums[blockIdx.x] = s[1023];
}

__global__ void k_scan2(int nb, int n) {
    if (threadIdx.x == 0) {
        int run = 0;
        for (int b = 0; b < nb; b++) { g_boff[b] = run; run += g_bsums[b]; }
        g_rowptr[n] = run;
    }
}

__global__ void k_scan3(int n) {
    int i = blockIdx.x * blockDim.x + threadIdx.x;
    if (i < n) {
        int v = g_incl[i] - g_deg[i] + g_boff[i >> 10]; // exclusive
        g_rowptr[i] = v;
        g_cursor[i] = v;
    }
}

__global__ void k_fill(const void* __restrict__ ei, int e, int n) {
    int i = blockIdx.x * blockDim.x + threadIdx.x;
    if (i < e) {
        int s = edge_at(ei, (size_t)i);
        int d = edge_at(ei, (size_t)e + i);
        if ((unsigned)s < (unsigned)n && (unsigned)d < (unsigned)n) {
            int p = atomicAdd(&g_cursor[d], 1);
            if ((unsigned)p < (unsigned)ECAP) g_col[p] = s;
        }
    }
}

// ------------------------------------------------------------------
// Agg1: warp per node.
// a1[i] = relu(dinv[i] * (sum_{j in in(i)} dinv[j]*h1[j] + dinv[i]*h1[i]) + b1)
__global__ void k_agg1(const float* __restrict__ b1, int n) {
    int warp = (blockIdx.x * blockDim.x + threadIdx.x) >> 5;
    int lane = threadIdx.x & 31;
    if (warp >= n) return;
    int beg = g_rowptr[warp], end = g_rowptr[warp + 1];
    const float4* h4 = (const float4*)g_h1;
    float di = g_dinv[warp];
    float4 self = h4[(size_t)warp * 32 + lane];
    float4 acc;
    acc.x = self.x * di; acc.y = self.y * di;
    acc.z = self.z * di; acc.w = self.w * di;
    for (int e = beg; e < end; e++) {
        int j = g_col[e];
        float dj = g_dinv[j];
        float4 v = h4[(size_t)j * 32 + lane];
        FMA4(acc, v, dj);
    }
    float4 b = ((const float4*)b1)[lane];
    float4 o;
    o.x = fmaxf(fmaf(acc.x, di, b.x), 0.f);
    o.y = fmaxf(fmaf(acc.y, di, b.y), 0.f);
    o.z = fmaxf(fmaf(acc.z, di, b.z), 0.f);
    o.w = fmaxf(fmaf(acc.w, di, b.w), 0.f);
    ((float4*)g_a1)[(size_t)warp * 32 + lane] = o;
}

// ------------------------------------------------------------------
// GEMM2: h2 = (a1 @ W2) * dinv[row].  Warp per row; lane l owns k=4l..4l+3.
__global__ void k_gemm2(const float* __restrict__ W2, int n) {
    __shared__ float W2s[DH * DOUT]; // 8KB
    for (int i = threadIdx.x; i < DH * DOUT; i += blockDim.x) W2s[i] = W2[i];
    __syncthreads();
    int warp = (blockIdx.x * blockDim.x + threadIdx.x) >> 5;
    int lane = threadIdx.x & 31;
    if (warp >= n) return;
    float4 xv = ((const float4*)g_a1)[(size_t)warp * 32 + lane];
    float xs[4] = {xv.x, xv.y, xv.z, xv.w};
    float4 c0 = make_float4(0,0,0,0), c1 = c0, c2 = c0, c3 = c0;
    int k0 = lane * 4;
    #pragma unroll
    for (int kk = 0; kk < 4; kk++) {
        const float4* wrow = (const float4*)(W2s + (k0 + kk) * DOUT);
        float s = xs[kk];
        float4 q0 = wrow[0], q1 = wrow[1], q2 = wrow[2], q3 = wrow[3];
        FMA4(c0, q0, s);
        FMA4(c1, q1, s);
        FMA4(c2, q2, s);
        FMA4(c3, q3, s);
    }
    float v[16] = {c0.x,c0.y,c0.z,c0.w, c1.x,c1.y,c1.z,c1.w,
                   c2.x,c2.y,c2.z,c2.w, c3.x,c3.y,c3.z,c3.w};
    #pragma unroll
    for (int off = 16; off >= 1; off >>= 1) {
        #pragma unroll
        for (int o = 0; o < 16; o++)
            v[o] += __shfl_xor_sync(0xffffffffu, v[o], off);
    }
    if (lane < 16) {
        float di = g_dinv[warp];
        g_h2[(size_t)warp * DOUT + lane] = v[lane] * di;
    }
}

// ------------------------------------------------------------------
// Agg2 + bias + log_softmax. Warp per node; lanes split edges in halves.
__global__ void k_agg2(const float* __restrict__ b2, float* __restrict__ out, int n) {
    int warp = (blockIdx.x * blockDim.x + threadIdx.x) >> 5;
    int lane = threadIdx.x & 31;
    if (warp >= n) return;
    int c = lane & 15, half = lane >> 4;
    int beg = g_rowptr[warp], end = g_rowptr[warp + 1];
    float acc = (half == 0) ? g_h2[(size_t)warp * DOUT + c] : 0.f; // self
    for (int e = beg + half; e < end; e += 2) {
        int j = g_col[e];
        acc += g_h2[(size_t)j * DOUT + c];
    }
    acc += __shfl_xor_sync(0xffffffffu, acc, 16);
    float di = g_dinv[warp];
    float logit = fmaf(acc, di, b2[c]);
    float m = logit;
    #pragma unroll
    for (int off = 8; off >= 1; off >>= 1)
        m = fmaxf(m, __shfl_xor_sync(0xffffffffu, m, off));
    float ex = expf(logit - m);
    float s = ex;
    #pragma unroll
    for (int off = 8; off >= 1; off >>= 1)
        s += __shfl_xor_sync(0xffffffffu, s, off);
    if (half == 0)
        out[(size_t)warp * DOUT + c] = logit - m - logf(s);
}

// ------------------------------------------------------------------
extern "C" void kernel_launch(void* const* d_in, const int* in_sizes, int n_in,
                              void* d_out, int out_size) {
    const float* x  = (const float*)d_in[0];
    const void*  ei = d_in[1];                 // int32 or int64, detected on device
    const float* W1 = (const float*)d_in[2];
    const float* b1 = (const float*)d_in[3];
    const float* W2 = (const float*)d_in[4];
    const float* b2 = (const float*)d_in[5];
    float* out = (float*)d_out;

    int n = in_sizes[0] / DIN;  // 100000
    int e = in_sizes[1] / 2;    // 1600000

    // init (zero degrees + dtype detect)
    k_init<<<(n + 255) / 256, 256>>>((const int*)ei, e, n);

    // fused GEMM1 + degree histogram (independent work, one launch)
    int g1 = (n + 127) / 128;
    k_gemm1_deg<<<g1 + GD_BLOCKS, 256>>>(x, W1, ei, e, n, g1);

    // CSR build
    int nb = (n + 1023) / 1024;
    k_scan1<<<nb, 1024>>>(n);
    k_scan2<<<1, 32>>>(nb, n);
    k_scan3<<<(n + 255) / 256, 256>>>(n);
    k_fill <<<(e + 255) / 256, 256>>>(ei, e, n);

    // layer 1 aggregation
    k_agg1 <<<(n + 7) / 8, 256>>>(b1, n);

    // layer 2 + log_softmax
    k_gemm2<<<(n + 7) / 8, 256>>>(W2, n);
    k_agg2 <<<(n + 7) / 8, 256>>>(b2, out, n);
}

// round 8
// speedup vs baseline: 1.0175x; 1.0175x over previous
#include <cuda_runtime.h>
#include <math.h>

#define DIN  128
#define DH   128
#define DOUT 16
#define NCAP 100352
#define ECAP 1600128

// ---- scratch (static __device__ per harness rules) ----
__device__ int   g_is64;            // 1 if edge_index is int64, 0 if int32
__device__ int   g_deg[NCAP];
__device__ float g_dinv[NCAP];
__device__ int   g_incl[NCAP];
__device__ int   g_bsums[256];
__device__ int   g_boff[256];
__device__ int   g_rowptr[NCAP + 1];
__device__ int   g_cursor[NCAP];
__device__ int   g_col[ECAP];
__device__ __align__(16) float g_h1[(size_t)NCAP * DH];   // (x@W1)*dinv[row]
__device__ __align__(16) float g_a1[(size_t)NCAP * DH];   // relu(agg1 + b1)
__device__ __align__(16) float g_h2[(size_t)NCAP * DOUT]; // (a1@W2)*dinv[row]

// ------------------------------------------------------------------
// packed fp32x2 helpers (sm_100+): ptxas never auto-fuses these.
__device__ __forceinline__ unsigned long long ffma2(unsigned long long a,
                                                    unsigned long long b,
                                                    unsigned long long c) {
    unsigned long long d;
    asm("fma.rn.f32x2 %0, %1, %2, %3;" : "=l"(d) : "l"(a), "l"(b), "l"(c));
    return d;
}
__device__ __forceinline__ unsigned long long mul2(unsigned long long a,
                                                   unsigned long long b) {
    unsigned long long d;
    asm("mul.rn.f32x2 %0, %1, %2;" : "=l"(d) : "l"(a), "l"(b));
    return d;
}
__device__ __forceinline__ unsigned long long pack2(float v) {
    unsigned long long d;
    asm("mov.b64 %0, {%1, %1};" : "=l"(d) : "f"(v));
    return d;
}

// ------------------------------------------------------------------
// init: zero degree array; block 0 also detects edge_index dtype
// (int64 => high word of every entry is 0 since indices < 100K).
__global__ void k_init(const int* __restrict__ ei32, int e, int n) {
    int i = blockIdx.x * blockDim.x + threadIdx.x;
    if (i < n) g_deg[i] = 0;
    if (blockIdx.x == 0) {
        __shared__ int nz;
        if (threadIdx.x == 0) nz = 0;
        __syncthreads();
        int lim = (e < 4096) ? e : 4096;
        for (int t = threadIdx.x; t < lim; t += blockDim.x)
            if (ei32[2 * t + 1] != 0) nz = 1;   // benign race
        __syncthreads();
        if (threadIdx.x == 0) g_is64 = (nz == 0) ? 1 : 0;
    }
}

__device__ __forceinline__ int edge_at(const void* ei, size_t pos) {
    if (g_is64) return (int)((const long long*)ei)[pos];
    return ((const int*)ei)[pos];
}

__global__ void k_degree(const void* __restrict__ ei, int e, int n) {
    int i = blockIdx.x * blockDim.x + threadIdx.x;
    if (i < e) {
        int d = edge_at(ei, (size_t)e + i);
        if ((unsigned)d < (unsigned)n) atomicAdd(&g_deg[d], 1);
    }
}

// block-level inclusive scan (1024 elems / block) + dinv computation
__global__ void k_scan1(int n) {
    __shared__ int s[1024];
    int i = blockIdx.x * 1024 + threadIdx.x;
    int d = (i < n) ? g_deg[i] : 0;
    s[threadIdx.x] = d;
    if (i < n) g_dinv[i] = rsqrtf((float)(d + 1)); // +1 self loop
    __syncthreads();
    for (int off = 1; off < 1024; off <<= 1) {
        int t = (threadIdx.x >= off) ? s[threadIdx.x - off] : 0;
        __syncthreads();
        s[threadIdx.x] += t;
        __syncthreads();
    }
    if (i < n) g_incl[i] = s[threadIdx.x];
    if (threadIdx.x == 1023) g_bsums[blockIdx.x] = s[1023];
}

// parallel scan over the (<=128) per-block sums
__global__ void k_scan2(int nb, int n) {
    __shared__ int s[128];
    int tid = threadIdx.x;
    int v = (tid < nb) ? g_bsums[tid] : 0;
    s[tid] = v;
    __syncthreads();
    for (int off = 1; off < 128; off <<= 1) {
        int t = (tid >= off) ? s[tid - off] : 0;
        __syncthreads();
        s[tid] += t;
        __syncthreads();
    }
    if (tid < nb) g_boff[tid] = s[tid] - v;       // exclusive
    if (tid == 127) g_rowptr[n] = s[127];
}

__global__ void k_scan3(int n) {
    int i = blockIdx.x * blockDim.x + threadIdx.x;
    if (i < n) {
        int v = g_incl[i] - g_deg[i] + g_boff[i >> 10]; // exclusive
        g_rowptr[i] = v;
        g_cursor[i] = v;
    }
}

__global__ void k_fill(const void* __restrict__ ei, int e, int n) {
    int i = blockIdx.x * blockDim.x + threadIdx.x;
    if (i < e) {
        int s = edge_at(ei, (size_t)i);
        int d = edge_at(ei, (size_t)e + i);
        if ((unsigned)s < (unsigned)n && (unsigned)d < (unsigned)n) {
            int p = atomicAdd(&g_cursor[d], 1);
            if ((unsigned)p < (unsigned)ECAP) g_col[p] = s;
        }
    }
}

// ------------------------------------------------------------------
#define FMA4(acc, vec, scal) do { \
    (acc).x = fmaf((scal), (vec).x, (acc).x); \
    (acc).y = fmaf((scal), (vec).y, (acc).y); \
    (acc).z = fmaf((scal), (vec).z, (acc).z); \
    (acc).w = fmaf((scal), (vec).w, (acc).w); } while (0)

#define KC 32   // k-chunk size for GEMM1

// GEMM1: h1 = (x @ W1) * dinv[row]  using packed fma.rn.f32x2.
// 128x128 block tile, 256 threads, 8 rows x 8 cols (4 f32x2 pairs) per thread.
__global__ void __launch_bounds__(256, 1) k_gemm1(const float* __restrict__ x,
                                                  const float* __restrict__ W1, int n) {
    __shared__ float Ws[KC * DH];    // 16KB
    __shared__ float Xs[128 * KC];   // 16KB
    int row0 = blockIdx.x * 128;

    int tx = threadIdx.x & 15;   // col group: cols tx*8 .. tx*8+7
    int ty = threadIdx.x >> 4;   // row group: rows ty*8 .. ty*8+7
    unsigned long long acc[8][4];
    #pragma unroll
    for (int r = 0; r < 8; r++)
        #pragma unroll
        for (int p = 0; p < 4; p++) acc[r][p] = 0ULL;

    const float4* W4 = (const float4*)W1;
    const float4* x4 = (const float4*)x;
    float4* Ws4 = (float4*)Ws;
    float4* Xs4 = (float4*)Xs;

    for (int kc = 0; kc < DIN / KC; kc++) {
        for (int i = threadIdx.x; i < KC * DH / 4; i += 256)
            Ws4[i] = W4[kc * (KC * DH / 4) + i];
        for (int i = threadIdx.x; i < 128 * KC / 4; i += 256) {
            int r = i >> 3, c = i & 7, gr = row0 + r;
            Xs4[i] = (gr < n) ? x4[(size_t)gr * 32 + kc * 8 + c]
                              : make_float4(0.f, 0.f, 0.f, 0.f);
        }
        __syncthreads();

        const float* wp = Ws + tx * 8;
        #pragma unroll
        for (int k = 0; k < KC; k++) {
            ulonglong2 w01 = *(const ulonglong2*)(wp + (size_t)k * 128);
            ulonglong2 w23 = *(const ulonglong2*)(wp + (size_t)k * 128 + 4);
            #pragma unroll
            for (int r = 0; r < 8; r++) {
                unsigned long long xp = pack2(Xs[(ty * 8 + r) * KC + k]);
                acc[r][0] = ffma2(xp, w01.x, acc[r][0]);
                acc[r][1] = ffma2(xp, w01.y, acc[r][1]);
                acc[r][2] = ffma2(xp, w23.x, acc[r][2]);
                acc[r][3] = ffma2(xp, w23.y, acc[r][3]);
            }
        }
        __syncthreads();
    }

    #pragma unroll
    for (int r = 0; r < 8; r++) {
        int row = row0 + ty * 8 + r;
        if (row < n) {
            unsigned long long dp = pack2(g_dinv[row]);
            ulonglong2 o0, o1;
            o0.x = mul2(acc[r][0], dp); o0.y = mul2(acc[r][1], dp);
            o1.x = mul2(acc[r][2], dp); o1.y = mul2(acc[r][3], dp);
            ulonglong2* hp = (ulonglong2*)&g_h1[(size_t)row * DH];
            hp[tx * 2]     = o0;
            hp[tx * 2 + 1] = o1;
        }
    }
}

// ------------------------------------------------------------------
// Agg1: warp per node, edge loop unrolled x4 for MLP.
// a1[i] = relu(dinv[i] * (h1[i] + sum_{j in in(i)} h1[j]) + b1)
__global__ void k_agg1(const float* __restrict__ b1, int n) {
    int warp = (blockIdx.x * blockDim.x + threadIdx.x) >> 5;
    int lane = threadIdx.x & 31;
    if (warp >= n) return;
    int beg = g_rowptr[warp], end = g_rowptr[warp + 1];
    const float4* h4 = (const float4*)g_h1;
    float4 acc = h4[(size_t)warp * 32 + lane];   // self (already *dinv[i])
    int e = beg;
    for (; e + 3 < end; e += 4) {
        int j0 = g_col[e], j1 = g_col[e + 1], j2 = g_col[e + 2], j3 = g_col[e + 3];
        float4 v0 = h4[(size_t)j0 * 32 + lane];
        float4 v1 = h4[(size_t)j1 * 32 + lane];
        float4 v2 = h4[(size_t)j2 * 32 + lane];
        float4 v3 = h4[(size_t)j3 * 32 + lane];
        float4 s01, s23;
        s01.x = v0.x + v1.x; s01.y = v0.y + v1.y; s01.z = v0.z + v1.z; s01.w = v0.w + v1.w;
        s23.x = v2.x + v3.x; s23.y = v2.y + v3.y; s23.z = v2.z + v3.z; s23.w = v2.w + v3.w;
        acc.x += s01.x + s23.x; acc.y += s01.y + s23.y;
        acc.z += s01.z + s23.z; acc.w += s01.w + s23.w;
    }
    for (; e < end; e++) {
        int j = g_col[e];
        float4 v = h4[(size_t)j * 32 + lane];
        acc.x += v.x; acc.y += v.y; acc.z += v.z; acc.w += v.w;
    }
    float di = g_dinv[warp];
    float4 b = ((const float4*)b1)[lane];
    float4 o;
    o.x = fmaxf(fmaf(acc.x, di, b.x), 0.f);
    o.y = fmaxf(fmaf(acc.y, di, b.y), 0.f);
    o.z = fmaxf(fmaf(acc.z, di, b.z), 0.f);
    o.w = fmaxf(fmaf(acc.w, di, b.w), 0.f);
    ((float4*)g_a1)[(size_t)warp * 32 + lane] = o;
}

// ------------------------------------------------------------------
// GEMM2: h2 = (a1 @ W2) * dinv[row].  Warp per row; lane l owns k=4l..4l+3.
__global__ void k_gemm2(const float* __restrict__ W2, int n) {
    __shared__ float W2s[DH * DOUT]; // 8KB
    for (int i = threadIdx.x; i < DH * DOUT; i += blockDim.x) W2s[i] = W2[i];
    __syncthreads();
    int warp = (blockIdx.x * blockDim.x + threadIdx.x) >> 5;
    int lane = threadIdx.x & 31;
    if (warp >= n) return;
    float4 xv = ((const float4*)g_a1)[(size_t)warp * 32 + lane];
    float xs[4] = {xv.x, xv.y, xv.z, xv.w};
    float4 c0 = make_float4(0,0,0,0), c1 = c0, c2 = c0, c3 = c0;
    int k0 = lane * 4;
    #pragma unroll
    for (int kk = 0; kk < 4; kk++) {
        const float4* wrow = (const float4*)(W2s + (k0 + kk) * DOUT);
        float s = xs[kk];
        float4 q0 = wrow[0], q1 = wrow[1], q2 = wrow[2], q3 = wrow[3];
        FMA4(c0, q0, s);
        FMA4(c1, q1, s);
        FMA4(c2, q2, s);
        FMA4(c3, q3, s);
    }
    float v[16] = {c0.x,c0.y,c0.z,c0.w, c1.x,c1.y,c1.z,c1.w,
                   c2.x,c2.y,c2.z,c2.w, c3.x,c3.y,c3.z,c3.w};
    #pragma unroll
    for (int off = 16; off >= 1; off >>= 1) {
        #pragma unroll
        for (int o = 0; o < 16; o++)
            v[o] += __shfl_xor_sync(0xffffffffu, v[o], off);
    }
    if (lane < 16) {
        float di = g_dinv[warp];
        g_h2[(size_t)warp * DOUT + lane] = v[lane] * di;
    }
}

// ------------------------------------------------------------------
// Agg2 + bias + log_softmax. Warp per node; lanes split edges in halves.
__global__ void k_agg2(const float* __restrict__ b2, float* __restrict__ out, int n) {
    int warp = (blockIdx.x * blockDim.x + threadIdx.x) >> 5;
    int lane = threadIdx.x & 31;
    if (warp >= n) return;
    int c = lane & 15, half = lane >> 4;
    int beg = g_rowptr[warp], end = g_rowptr[warp + 1];
    float acc = (half == 0) ? g_h2[(size_t)warp * DOUT + c] : 0.f; // self
    for (int e = beg + half; e < end; e += 2) {
        int j = g_col[e];
        acc += g_h2[(size_t)j * DOUT + c];
    }
    acc += __shfl_xor_sync(0xffffffffu, acc, 16);
    float di = g_dinv[warp];
    float logit = fmaf(acc, di, b2[c]);
    float m = logit;
    #pragma unroll
    for (int off = 8; off >= 1; off >>= 1)
        m = fmaxf(m, __shfl_xor_sync(0xffffffffu, m, off));
    float ex = expf(logit - m);
    float s = ex;
    #pragma unroll
    for (int off = 8; off >= 1; off >>= 1)
        s += __shfl_xor_sync(0xffffffffu, s, off);
    if (half == 0)
        out[(size_t)warp * DOUT + c] = logit - m - logf(s);
}

// ------------------------------------------------------------------
extern "C" void kernel_launch(void* const* d_in, const int* in_sizes, int n_in,
                              void* d_out, int out_size) {
    const float* x  = (const float*)d_in[0];
    const void*  ei = d_in[1];                 // int32 or int64, detected on device
    const float* W1 = (const float*)d_in[2];
    const float* b1 = (const float*)d_in[3];
    const float* W2 = (const float*)d_in[4];
    const float* b2 = (const float*)d_in[5];
    float* out = (float*)d_out;

    int n = in_sizes[0] / DIN;  // 100000
    int e = in_sizes[1] / 2;    // 1600000

    // graph build
    k_init  <<<(n + 255) / 256, 256>>>((const int*)ei, e, n);
    k_degree<<<(e + 255) / 256, 256>>>(ei, e, n);
    int nb = (n + 1023) / 1024;
    k_scan1 <<<nb, 1024>>>(n);
    k_scan2 <<<1, 128>>>(nb, n);
    k_scan3 <<<(n + 255) / 256, 256>>>(n);
    k_fill  <<<(e + 255) / 256, 256>>>(ei, e, n);

    // layer 1
    k_gemm1<<<(n + 127) / 128, 256>>>(x, W1, n);
    k_agg1 <<<(n + 7) / 8, 256>>>(b1, n);

    // layer 2 + log_softmax
    k_gemm2<<<(n + 7) / 8, 256>>>(W2, n);
    k_agg2 <<<(n + 7) / 8, 256>>>(b2, out, n);
}

// round 9
// speedup vs baseline: 1.1266x; 1.1073x over previous
#include <cuda_runtime.h>
#include <math.h>

#define DIN  128
#define DH   128
#define DOUT 16
#define NCAP 100352
#define ECAP 1600128

// ---- scratch (static __device__ per harness rules) ----
__device__ int   g_is64;            // 1 if edge_index is int64, 0 if int32
__device__ int   g_deg[NCAP];
__device__ float g_dinv[NCAP];
__device__ int   g_incl[NCAP];
__device__ int   g_bsums[256];
__device__ int   g_boff[256];
__device__ int   g_rowptr[NCAP + 1];
__device__ int   g_cursor[NCAP];
__device__ int   g_col[ECAP];
__device__ __align__(16) float g_h1[(size_t)NCAP * DH];   // (x@W1)*dinv[row]
__device__ __align__(16) float g_a1[(size_t)NCAP * DH];   // relu(agg1 + b1)
__device__ __align__(16) float g_h2[(size_t)NCAP * DOUT]; // (a1@W2)*dinv[row]

// ------------------------------------------------------------------
// init: zero degree array; block 0 also detects edge_index dtype
// (int64 => high word of every entry is 0 since indices < 100K).
__global__ void k_init(const int* __restrict__ ei32, int e, int n) {
    int i = blockIdx.x * blockDim.x + threadIdx.x;
    if (i < n) g_deg[i] = 0;
    if (blockIdx.x == 0) {
        __shared__ int nz;
        if (threadIdx.x == 0) nz = 0;
        __syncthreads();
        int lim = (e < 4096) ? e : 4096;
        for (int t = threadIdx.x; t < lim; t += blockDim.x)
            if (ei32[2 * t + 1] != 0) nz = 1;   // benign race
        __syncthreads();
        if (threadIdx.x == 0) g_is64 = (nz == 0) ? 1 : 0;
    }
}

__device__ __forceinline__ int edge_at(const void* ei, size_t pos) {
    if (g_is64) return (int)((const long long*)ei)[pos];
    return ((const int*)ei)[pos];
}

__global__ void k_degree(const void* __restrict__ ei, int e, int n) {
    int i = blockIdx.x * blockDim.x + threadIdx.x;
    if (i < e) {
        int d = edge_at(ei, (size_t)e + i);
        if ((unsigned)d < (unsigned)n) atomicAdd(&g_deg[d], 1);
    }
}

// block-level inclusive scan (1024 elems / block) + dinv computation
__global__ void k_scan1(int n) {
    __shared__ int s[1024];
    int i = blockIdx.x * 1024 + threadIdx.x;
    int d = (i < n) ? g_deg[i] : 0;
    s[threadIdx.x] = d;
    if (i < n) g_dinv[i] = rsqrtf((float)(d + 1)); // +1 self loop
    __syncthreads();
    for (int off = 1; off < 1024; off <<= 1) {
        int t = (threadIdx.x >= off) ? s[threadIdx.x - off] : 0;
        __syncthreads();
        s[threadIdx.x] += t;
        __syncthreads();
    }
    if (i < n) g_incl[i] = s[threadIdx.x];
    if (threadIdx.x == 1023) g_bsums[blockIdx.x] = s[1023];
}

// parallel scan over the (<=128) per-block sums
__global__ void k_scan2(int nb, int n) {
    __shared__ int s[128];
    int tid = threadIdx.x;
    int v = (tid < nb) ? g_bsums[tid] : 0;
    s[tid] = v;
    __syncthreads();
    for (int off = 1; off < 128; off <<= 1) {
        int t = (tid >= off) ? s[tid - off] : 0;
        __syncthreads();
        s[tid] += t;
        __syncthreads();
    }
    if (tid < nb) g_boff[tid] = s[tid] - v;       // exclusive
    if (tid == 127) g_rowptr[n] = s[127];
}

__global__ void k_scan3(int n) {
    int i = blockIdx.x * blockDim.x + threadIdx.x;
    if (i < n) {
        int v = g_incl[i] - g_deg[i] + g_boff[i >> 10]; // exclusive
        g_rowptr[i] = v;
        g_cursor[i] = v;
    }
}

__global__ void k_fill(const void* __restrict__ ei, int e, int n) {
    int i = blockIdx.x * blockDim.x + threadIdx.x;
    if (i < e) {
        int s = edge_at(ei, (size_t)i);
        int d = edge_at(ei, (size_t)e + i);
        if ((unsigned)s < (unsigned)n && (unsigned)d < (unsigned)n) {
            int p = atomicAdd(&g_cursor[d], 1);
            if ((unsigned)p < (unsigned)ECAP) g_col[p] = s;
        }
    }
}

// ------------------------------------------------------------------
// FMA4: acc += scal * vec  (parameter names must NOT collide with x/y/z/w)
#define FMA4(acc, vec, scal) do { \
    (acc).x = fmaf((scal), (vec).x, (acc).x); \
    (acc).y = fmaf((scal), (vec).y, (acc).y); \
    (acc).z = fmaf((scal), (vec).z, (acc).z); \
    (acc).w = fmaf((scal), (vec).w, (acc).w); } while (0)

#define KC 32   // k-chunk size for GEMM1

// GEMM1: h1 = (x @ W1) * dinv[row].  128x128 block tile, k chunked by 32,
// 32KB static smem, 256 threads, 8x8 micro-tile. (Proven R4 form — the
// f32x2 variant measured slower; FFMA2 appears to be half-rate per pair.)
__global__ void __launch_bounds__(256, 1) k_gemm1(const float* __restrict__ x,
                                                  const float* __restrict__ W1, int n) {
    __shared__ float Ws[KC * DH];    // 16KB
    __shared__ float Xs[128 * KC];   // 16KB
    int row0 = blockIdx.x * 128;

    int tx = threadIdx.x & 15;
    int ty = threadIdx.x >> 4;
    float4 a0[8], a1[8];
    #pragma unroll
    for (int r = 0; r < 8; r++) { a0[r] = make_float4(0,0,0,0); a1[r] = make_float4(0,0,0,0); }

    const float4* W4 = (const float4*)W1;
    const float4* x4 = (const float4*)x;
    float4* Ws4 = (float4*)Ws;
    float4* Xs4 = (float4*)Xs;

    for (int kc = 0; kc < DIN / KC; kc++) {
        for (int i = threadIdx.x; i < KC * DH / 4; i += 256)
            Ws4[i] = W4[kc * (KC * DH / 4) + i];
        for (int i = threadIdx.x; i < 128 * KC / 4; i += 256) {
            int r = i >> 3, c = i & 7, gr = row0 + r;
            Xs4[i] = (gr < n) ? x4[(size_t)gr * 32 + kc * 8 + c]
                              : make_float4(0.f, 0.f, 0.f, 0.f);
        }
        __syncthreads();

        const float* wp = Ws + tx * 8;
        #pragma unroll
        for (int k = 0; k < KC; k++) {
            float4 wv0 = *(const float4*)(wp + k * 128);
            float4 wv1 = *(const float4*)(wp + k * 128 + 4);
            #pragma unroll
            for (int r = 0; r < 8; r++) {
                float xv = Xs[(ty * 8 + r) * KC + k];
                FMA4(a0[r], wv0, xv);
                FMA4(a1[r], wv1, xv);
            }
        }
        __syncthreads();
    }

    #pragma unroll
    for (int r = 0; r < 8; r++) {
        int row = row0 + ty * 8 + r;
        if (row < n) {
            float dv = g_dinv[row];
            float4 o0 = a0[r], o1 = a1[r];
            o0.x *= dv; o0.y *= dv; o0.z *= dv; o0.w *= dv;
            o1.x *= dv; o1.y *= dv; o1.z *= dv; o1.w *= dv;
            float4* hp = (float4*)&g_h1[(size_t)row * DH];
            hp[tx * 2]     = o0;
            hp[tx * 2 + 1] = o1;
        }
    }
}

// ------------------------------------------------------------------
// Agg1: warp per node, edge loop unrolled x4 for MLP.
// a1[i] = relu(dinv[i] * (h1[i] + sum_{j in in(i)} h1[j]) + b1)
__global__ void k_agg1(const float* __restrict__ b1, int n) {
    int warp = (blockIdx.x * blockDim.x + threadIdx.x) >> 5;
    int lane = threadIdx.x & 31;
    if (warp >= n) return;
    int beg = g_rowptr[warp], end = g_rowptr[warp + 1];
    const float4* h4 = (const float4*)g_h1;
    float4 acc = h4[(size_t)warp * 32 + lane];   // self (already *dinv[i])
    int e = beg;
    for (; e + 3 < end; e += 4) {
        int j0 = g_col[e], j1 = g_col[e + 1], j2 = g_col[e + 2], j3 = g_col[e + 3];
        float4 v0 = h4[(size_t)j0 * 32 + lane];
        float4 v1 = h4[(size_t)j1 * 32 + lane];
        float4 v2 = h4[(size_t)j2 * 32 + lane];
        float4 v3 = h4[(size_t)j3 * 32 + lane];
        float4 s01, s23;
        s01.x = v0.x + v1.x; s01.y = v0.y + v1.y; s01.z = v0.z + v1.z; s01.w = v0.w + v1.w;
        s23.x = v2.x + v3.x; s23.y = v2.y + v3.y; s23.z = v2.z + v3.z; s23.w = v2.w + v3.w;
        acc.x += s01.x + s23.x; acc.y += s01.y + s23.y;
        acc.z += s01.z + s23.z; acc.w += s01.w + s23.w;
    }
    for (; e < end; e++) {
        int j = g_col[e];
        float4 v = h4[(size_t)j * 32 + lane];
        acc.x += v.x; acc.y += v.y; acc.z += v.z; acc.w += v.w;
    }
    float di = g_dinv[warp];
    float4 b = ((const float4*)b1)[lane];
    float4 o;
    o.x = fmaxf(fmaf(acc.x, di, b.x), 0.f);
    o.y = fmaxf(fmaf(acc.y, di, b.y), 0.f);
    o.z = fmaxf(fmaf(acc.z, di, b.z), 0.f);
    o.w = fmaxf(fmaf(acc.w, di, b.w), 0.f);
    ((float4*)g_a1)[(size_t)warp * 32 + lane] = o;
}

// ------------------------------------------------------------------
// GEMM2: h2 = (a1 @ W2) * dinv[row].  Warp per row; lane l owns k=4l..4l+3.
__global__ void k_gemm2(const float* __restrict__ W2, int n) {
    __shared__ float W2s[DH * DOUT]; // 8KB
    for (int i = threadIdx.x; i < DH * DOUT; i += blockDim.x) W2s[i] = W2[i];
    __syncthreads();
    int warp = (blockIdx.x * blockDim.x + threadIdx.x) >> 5;
    int lane = threadIdx.x & 31;
    if (warp >= n) return;
    float4 xv = ((const float4*)g_a1)[(size_t)warp * 32 + lane];
    float xs[4] = {xv.x, xv.y, xv.z, xv.w};
    float4 c0 = make_float4(0,0,0,0), c1 = c0, c2 = c0, c3 = c0;
    int k0 = lane * 4;
    #pragma unroll
    for (int kk = 0; kk < 4; kk++) {
        const float4* wrow = (const float4*)(W2s + (k0 + kk) * DOUT);
        float s = xs[kk];
        float4 q0 = wrow[0], q1 = wrow[1], q2 = wrow[2], q3 = wrow[3];
        FMA4(c0, q0, s);
        FMA4(c1, q1, s);
        FMA4(c2, q2, s);
        FMA4(c3, q3, s);
    }
    float v[16] = {c0.x,c0.y,c0.z,c0.w, c1.x,c1.y,c1.z,c1.w,
                   c2.x,c2.y,c2.z,c2.w, c3.x,c3.y,c3.z,c3.w};
    #pragma unroll
    for (int off = 16; off >= 1; off >>= 1) {
        #pragma unroll
        for (int o = 0; o < 16; o++)
            v[o] += __shfl_xor_sync(0xffffffffu, v[o], off);
    }
    if (lane < 16) {
        float di = g_dinv[warp];
        g_h2[(size_t)warp * DOUT + lane] = v[lane] * di;
    }
}

// ------------------------------------------------------------------
// Agg2 + bias + log_softmax. Warp per node; lanes split edges in halves.
__global__ void k_agg2(const float* __restrict__ b2, float* __restrict__ out, int n) {
    int warp = (blockIdx.x * blockDim.x + threadIdx.x) >> 5;
    int lane = threadIdx.x & 31;
    if (warp >= n) return;
    int c = lane & 15, half = lane >> 4;
    int beg = g_rowptr[warp], end = g_rowptr[warp + 1];
    float acc = (half == 0) ? g_h2[(size_t)warp * DOUT + c] : 0.f; // self
    for (int e = beg + half; e < end; e += 2) {
        int j = g_col[e];
        acc += g_h2[(size_t)j * DOUT + c];
    }
    acc += __shfl_xor_sync(0xffffffffu, acc, 16);
    float di = g_dinv[warp];
    float logit = fmaf(acc, di, b2[c]);
    float m = logit;
    #pragma unroll
    for (int off = 8; off >= 1; off >>= 1)
        m = fmaxf(m, __shfl_xor_sync(0xffffffffu, m, off));
    float ex = expf(logit - m);
    float s = ex;
    #pragma unroll
    for (int off = 8; off >= 1; off >>= 1)
        s += __shfl_xor_sync(0xffffffffu, s, off);
    if (half == 0)
        out[(size_t)warp * DOUT + c] = logit - m - logf(s);
}

// ------------------------------------------------------------------
extern "C" void kernel_launch(void* const* d_in, const int* in_sizes, int n_in,
                              void* d_out, int out_size) {
    const float* x  = (const float*)d_in[0];
    const void*  ei = d_in[1];                 // int32 or int64, detected on device
    const float* W1 = (const float*)d_in[2];
    const float* b1 = (const float*)d_in[3];
    const float* W2 = (const float*)d_in[4];
    const float* b2 = (const float*)d_in[5];
    float* out = (float*)d_out;

    int n = in_sizes[0] / DIN;  // 100000
    int e = in_sizes[1] / 2;    // 1600000

    // graph build; k_gemm1 placed at launch index 3 so the harness's fixed
    // ncu window (-s 5 -c 1, two harness launches precede ours) profiles it.
    k_init  <<<(n + 255) / 256, 256>>>((const int*)ei, e, n);
    k_degree<<<(e + 255) / 256, 256>>>(ei, e, n);
    int nb = (n + 1023) / 1024;
    k_scan1 <<<nb, 1024>>>(n);                     // produces dinv
    k_gemm1 <<<(n + 127) / 128, 256>>>(x, W1, n);  // needs x, W1, dinv only
    k_scan2 <<<1, 128>>>(nb, n);
    k_scan3 <<<(n + 255) / 256, 256>>>(n);
    k_fill  <<<(e + 255) / 256, 256>>>(ei, e, n);

    // layer 1 aggregation
    k_agg1 <<<(n + 7) / 8, 256>>>(b1, n);

    // layer 2 + log_softmax
    k_gemm2<<<(n + 7) / 8, 256>>>(W2, n);
    k_agg2 <<<(n + 7) / 8, 256>>>(b2, out, n);
}

// round 10
// speedup vs baseline: 1.1273x; 1.0006x over previous
#include <cuda_runtime.h>
#include <math.h>

#define DIN  128
#define DH   128
#define DOUT 16
#define NCAP 100352
#define ECAP 1600128

// ---- scratch (static __device__ per harness rules) ----
__device__ int   g_is64;            // 1 if edge_index is int64, 0 if int32
__device__ int   g_deg[NCAP];
__device__ float g_dinv[NCAP];
__device__ int   g_incl[NCAP];
__device__ int   g_bsums[256];
__device__ int   g_boff[256];
__device__ int   g_rowptr[NCAP + 1];
__device__ int   g_cursor[NCAP];
__device__ int   g_col[ECAP];
__device__ __align__(16) float g_h1[(size_t)NCAP * DH];   // (x@W1)*dinv[row]
__device__ __align__(16) float g_h2[(size_t)NCAP * DOUT]; // (a1@W2)*dinv[row]

// ------------------------------------------------------------------
// init: zero degree array; block 0 also detects edge_index dtype
// (int64 => high word of every entry is 0 since indices < 100K).
__global__ void k_init(const int* __restrict__ ei32, int e, int n) {
    int i = blockIdx.x * blockDim.x + threadIdx.x;
    if (i < n) g_deg[i] = 0;
    if (blockIdx.x == 0) {
        __shared__ int nz;
        if (threadIdx.x == 0) nz = 0;
        __syncthreads();
        int lim = (e < 4096) ? e : 4096;
        for (int t = threadIdx.x; t < lim; t += blockDim.x)
            if (ei32[2 * t + 1] != 0) nz = 1;   // benign race
        __syncthreads();
        if (threadIdx.x == 0) g_is64 = (nz == 0) ? 1 : 0;
    }
}

__device__ __forceinline__ int edge_at(const void* ei, size_t pos) {
    if (g_is64) return (int)((const long long*)ei)[pos];
    return ((const int*)ei)[pos];
}

__global__ void k_degree(const void* __restrict__ ei, int e, int n) {
    int i = blockIdx.x * blockDim.x + threadIdx.x;
    if (i < e) {
        int d = edge_at(ei, (size_t)e + i);
        if ((unsigned)d < (unsigned)n) atomicAdd(&g_deg[d], 1);
    }
}

// block-level inclusive scan (1024 elems / block) + dinv computation
__global__ void k_scan1(int n) {
    __shared__ int s[1024];
    int i = blockIdx.x * 1024 + threadIdx.x;
    int d = (i < n) ? g_deg[i] : 0;
    s[threadIdx.x] = d;
    if (i < n) g_dinv[i] = rsqrtf((float)(d + 1)); // +1 self loop
    __syncthreads();
    for (int off = 1; off < 1024; off <<= 1) {
        int t = (threadIdx.x >= off) ? s[threadIdx.x - off] : 0;
        __syncthreads();
        s[threadIdx.x] += t;
        __syncthreads();
    }
    if (i < n) g_incl[i] = s[threadIdx.x];
    if (threadIdx.x == 1023) g_bsums[blockIdx.x] = s[1023];
}

// parallel scan over the (<=128) per-block sums
__global__ void k_scan2(int nb, int n) {
    __shared__ int s[128];
    int tid = threadIdx.x;
    int v = (tid < nb) ? g_bsums[tid] : 0;
    s[tid] = v;
    __syncthreads();
    for (int off = 1; off < 128; off <<= 1) {
        int t = (tid >= off) ? s[tid - off] : 0;
        __syncthreads();
        s[tid] += t;
        __syncthreads();
    }
    if (tid < nb) g_boff[tid] = s[tid] - v;       // exclusive
    if (tid == 127) g_rowptr[n] = s[127];
}

__global__ void k_scan3(int n) {
    int i = blockIdx.x * blockDim.x + threadIdx.x;
    if (i < n) {
        int v = g_incl[i] - g_deg[i] + g_boff[i >> 10]; // exclusive
        g_rowptr[i] = v;
        g_cursor[i] = v;
    }
}

// ------------------------------------------------------------------
// FMA4: acc += scal * vec  (parameter names must NOT collide with x/y/z/w)
#define FMA4(acc, vec, scal) do { \
    (acc).x = fmaf((scal), (vec).x, (acc).x); \
    (acc).y = fmaf((scal), (vec).y, (acc).y); \
    (acc).z = fmaf((scal), (vec).z, (acc).z); \
    (acc).w = fmaf((scal), (vec).w, (acc).w); } while (0)

#define KC 32          // k-chunk size for GEMM1
#define GF_BLOCKS 256  // CSR-fill blocks placed FIRST in the fused grid

// Fused: blocks [0, GF_BLOCKS) do the CSR fill (memory/atomic-bound);
// blocks [GF_BLOCKS, ...) do GEMM1: h1 = (x @ W1) * dinv[row] (fma-bound).
// Independent work on complementary pipes; fill blocks go first so they
// start in wave 1 and finish under the GEMM (R6's tail mistake inverted).
__global__ void __launch_bounds__(256, 1) k_fill_gemm1(const float* __restrict__ x,
                                                       const float* __restrict__ W1,
                                                       const void* __restrict__ ei,
                                                       int e, int n) {
    __shared__ float Ws[KC * DH];    // 16KB
    __shared__ float Xs[128 * KC];   // 16KB

    if (blockIdx.x < GF_BLOCKS) {
        // ---- CSR fill path ----
        int i0 = blockIdx.x * blockDim.x + threadIdx.x;
        int stride = GF_BLOCKS * blockDim.x;
        for (int i = i0; i < e; i += stride) {
            int s = edge_at(ei, (size_t)i);
            int d = edge_at(ei, (size_t)e + i);
            if ((unsigned)s < (unsigned)n && (unsigned)d < (unsigned)n) {
                int p = atomicAdd(&g_cursor[d], 1);
                if ((unsigned)p < (unsigned)ECAP) g_col[p] = s;
            }
        }
        return;
    }

    // ---- GEMM1 path ----
    int row0 = (blockIdx.x - GF_BLOCKS) * 128;
    int tx = threadIdx.x & 15;
    int ty = threadIdx.x >> 4;
    float4 a0[8], a1[8];
    #pragma unroll
    for (int r = 0; r < 8; r++) { a0[r] = make_float4(0,0,0,0); a1[r] = make_float4(0,0,0,0); }

    const float4* W4 = (const float4*)W1;
    const float4* x4 = (const float4*)x;
    float4* Ws4 = (float4*)Ws;
    float4* Xs4 = (float4*)Xs;

    for (int kc = 0; kc < DIN / KC; kc++) {
        for (int i = threadIdx.x; i < KC * DH / 4; i += 256)
            Ws4[i] = W4[kc * (KC * DH / 4) + i];
        for (int i = threadIdx.x; i < 128 * KC / 4; i += 256) {
            int r = i >> 3, c = i & 7, gr = row0 + r;
            Xs4[i] = (gr < n) ? x4[(size_t)gr * 32 + kc * 8 + c]
                              : make_float4(0.f, 0.f, 0.f, 0.f);
        }
        __syncthreads();

        const float* wp = Ws + tx * 8;
        #pragma unroll
        for (int k = 0; k < KC; k++) {
            float4 wv0 = *(const float4*)(wp + k * 128);
            float4 wv1 = *(const float4*)(wp + k * 128 + 4);
            #pragma unroll
            for (int r = 0; r < 8; r++) {
                float xv = Xs[(ty * 8 + r) * KC + k];
                FMA4(a0[r], wv0, xv);
                FMA4(a1[r], wv1, xv);
            }
        }
        __syncthreads();
    }

    #pragma unroll
    for (int r = 0; r < 8; r++) {
        int row = row0 + ty * 8 + r;
        if (row < n) {
            float dv = g_dinv[row];
            float4 o0 = a0[r], o1 = a1[r];
            o0.x *= dv; o0.y *= dv; o0.z *= dv; o0.w *= dv;
            o1.x *= dv; o1.y *= dv; o1.z *= dv; o1.w *= dv;
            float4* hp = (float4*)&g_h1[(size_t)row * DH];
            hp[tx * 2]     = o0;
            hp[tx * 2 + 1] = o1;
        }
    }
}

// ------------------------------------------------------------------
// Fused Agg1 + GEMM2: warp per node.
// a1_row = relu(dinv[i]*(h1[i] + sum_j h1[j]) + b1)  — held in registers,
// lane l owns features 4l..4l+3, which is exactly GEMM2's k-ownership.
// Then h2[i] = (a1_row @ W2) * dinv[i], reduced via shfl tree.
__global__ void k_agg1_gemm2(const float* __restrict__ b1,
                             const float* __restrict__ W2, int n) {
    __shared__ float W2s[DH * DOUT]; // 8KB
    for (int i = threadIdx.x; i < DH * DOUT; i += blockDim.x) W2s[i] = W2[i];
    __syncthreads();

    int warp = (blockIdx.x * blockDim.x + threadIdx.x) >> 5;
    int lane = threadIdx.x & 31;
    if (warp >= n) return;

    // ---- agg1 (x4-unrolled gather over pre-scaled h1) ----
    int beg = g_rowptr[warp], end = g_rowptr[warp + 1];
    const float4* h4 = (const float4*)g_h1;
    float4 acc = h4[(size_t)warp * 32 + lane];   // self (already *dinv[i])
    int e = beg;
    for (; e + 3 < end; e += 4) {
        int j0 = g_col[e], j1 = g_col[e + 1], j2 = g_col[e + 2], j3 = g_col[e + 3];
        float4 v0 = h4[(size_t)j0 * 32 + lane];
        float4 v1 = h4[(size_t)j1 * 32 + lane];
        float4 v2 = h4[(size_t)j2 * 32 + lane];
        float4 v3 = h4[(size_t)j3 * 32 + lane];
        float4 s01, s23;
        s01.x = v0.x + v1.x; s01.y = v0.y + v1.y; s01.z = v0.z + v1.z; s01.w = v0.w + v1.w;
        s23.x = v2.x + v3.x; s23.y = v2.y + v3.y; s23.z = v2.z + v3.z; s23.w = v2.w + v3.w;
        acc.x += s01.x + s23.x; acc.y += s01.y + s23.y;
        acc.z += s01.z + s23.z; acc.w += s01.w + s23.w;
    }
    for (; e < end; e++) {
        int j = g_col[e];
        float4 v = h4[(size_t)j * 32 + lane];
        acc.x += v.x; acc.y += v.y; acc.z += v.z; acc.w += v.w;
    }
    float di = g_dinv[warp];
    float4 b = ((const float4*)b1)[lane];
    float xs[4];
    xs[0] = fmaxf(fmaf(acc.x, di, b.x), 0.f);
    xs[1] = fmaxf(fmaf(acc.y, di, b.y), 0.f);
    xs[2] = fmaxf(fmaf(acc.z, di, b.z), 0.f);
    xs[3] = fmaxf(fmaf(acc.w, di, b.w), 0.f);

    // ---- gemm2 (register-resident a1 row; lane l owns k=4l..4l+3) ----
    float4 c0 = make_float4(0,0,0,0), c1 = c0, c2 = c0, c3 = c0;
    int k0 = lane * 4;
    #pragma unroll
    for (int kk = 0; kk < 4; kk++) {
        const float4* wrow = (const float4*)(W2s + (k0 + kk) * DOUT);
        float s = xs[kk];
        float4 q0 = wrow[0], q1 = wrow[1], q2 = wrow[2], q3 = wrow[3];
        FMA4(c0, q0, s);
        FMA4(c1, q1, s);
        FMA4(c2, q2, s);
        FMA4(c3, q3, s);
    }
    float v[16] = {c0.x,c0.y,c0.z,c0.w, c1.x,c1.y,c1.z,c1.w,
                   c2.x,c2.y,c2.z,c2.w, c3.x,c3.y,c3.z,c3.w};
    #pragma unroll
    for (int off = 16; off >= 1; off >>= 1) {
        #pragma unroll
        for (int o = 0; o < 16; o++)
            v[o] += __shfl_xor_sync(0xffffffffu, v[o], off);
    }
    if (lane < 16)
        g_h2[(size_t)warp * DOUT + lane] = v[lane] * di;
}

// ------------------------------------------------------------------
// Agg2 + bias + log_softmax. Warp per node; lanes split edges in halves.
__global__ void k_agg2(const float* __restrict__ b2, float* __restrict__ out, int n) {
    int warp = (blockIdx.x * blockDim.x + threadIdx.x) >> 5;
    int lane = threadIdx.x & 31;
    if (warp >= n) return;
    int c = lane & 15, half = lane >> 4;
    int beg = g_rowptr[warp], end = g_rowptr[warp + 1];
    float acc = (half == 0) ? g_h2[(size_t)warp * DOUT + c] : 0.f; // self
    for (int e = beg + half; e < end; e += 2) {
        int j = g_col[e];
        acc += g_h2[(size_t)j * DOUT + c];
    }
    acc += __shfl_xor_sync(0xffffffffu, acc, 16);
    float di = g_dinv[warp];
    float logit = fmaf(acc, di, b2[c]);
    float m = logit;
    #pragma unroll
    for (int off = 8; off >= 1; off >>= 1)
        m = fmaxf(m, __shfl_xor_sync(0xffffffffu, m, off));
    float ex = expf(logit - m);
    float s = ex;
    #pragma unroll
    for (int off = 8; off >= 1; off >>= 1)
        s += __shfl_xor_sync(0xffffffffu, s, off);
    if (half == 0)
        out[(size_t)warp * DOUT + c] = logit - m - logf(s);
}

// ------------------------------------------------------------------
extern "C" void kernel_launch(void* const* d_in, const int* in_sizes, int n_in,
                              void* d_out, int out_size) {
    const float* x  = (const float*)d_in[0];
    const void*  ei = d_in[1];                 // int32 or int64, detected on device
    const float* W1 = (const float*)d_in[2];
    const float* b1 = (const float*)d_in[3];
    const float* W2 = (const float*)d_in[4];
    const float* b2 = (const float*)d_in[5];
    float* out = (float*)d_out;

    int n = in_sizes[0] / DIN;  // 100000
    int e = in_sizes[1] / 2;    // 1600000

    // graph build
    k_init  <<<(n + 255) / 256, 256>>>((const int*)ei, e, n);
    k_degree<<<(e + 255) / 256, 256>>>(ei, e, n);
    int nb = (n + 1023) / 1024;
    k_scan1 <<<nb, 1024>>>(n);
    k_scan2 <<<1, 128>>>(nb, n);
    k_scan3 <<<(n + 255) / 256, 256>>>(n);

    // fused CSR-fill (first GF_BLOCKS) + GEMM1 (rest)
    int g1 = (n + 127) / 128;
    k_fill_gemm1<<<GF_BLOCKS + g1, 256>>>(x, W1, ei, e, n);

    // fused layer-1 aggregation + layer-2 GEMM
    k_agg1_gemm2<<<(n + 7) / 8, 256>>>(b1, W2, n);

    // layer-2 aggregation + log_softmax
    k_agg2<<<(n + 7) / 8, 256>>>(b2, out, n);
}